// round 1
// baseline (speedup 1.0000x reference)
#include <cuda_runtime.h>

#define NCLASS 1024
#define DIM    256
#define KSZ    8
#define NSAMP  8192

// scratch (no allocations allowed)
__device__ float g_centers[NCLASS * DIM];
__device__ float g_sq[NCLASS];
__device__ float g_acc[2];   // [0] = dist_pc sum, [1] = hinge sum (upper triangle)

__global__ void zero_kernel() {
    if (threadIdx.x < 2) g_acc[threadIdx.x] = 0.0f;
}

// One block per class: 8 warps <-> 8 rows. Normalize rows, build center,
// normalize center, per-row distance, accumulate dist_pc sum.
__global__ void class_kernel(const float* __restrict__ x) {
    int c = blockIdx.x;
    int t = threadIdx.x;
    int w = t >> 5, lane = t & 31;

    __shared__ float xn[KSZ][DIM];
    __shared__ float cen[DIM];
    __shared__ float red[KSZ];
    __shared__ float s_cinv;

    const float* row = x + (size_t)(c * KSZ + w) * DIM;
    float v[8];
    float ss = 0.0f;
#pragma unroll
    for (int i = 0; i < 8; i++) {
        v[i] = row[lane + 32 * i];
        ss += v[i] * v[i];
    }
#pragma unroll
    for (int o = 16; o; o >>= 1) ss += __shfl_xor_sync(0xffffffffu, ss, o);
    float inv = rsqrtf(ss);
#pragma unroll
    for (int i = 0; i < 8; i++) {
        v[i] *= inv;
        xn[w][lane + 32 * i] = v[i];
    }
    __syncthreads();

    // center (each of 256 threads owns one dim)
    float cs = 0.0f;
#pragma unroll
    for (int r = 0; r < KSZ; r++) cs += xn[r][t];
    cs *= (1.0f / KSZ);
    cen[t] = cs;
    g_centers[c * DIM + t] = cs;

    // ||center||^2 via block reduce
    float c2 = cs * cs;
#pragma unroll
    for (int o = 16; o; o >>= 1) c2 += __shfl_xor_sync(0xffffffffu, c2, o);
    if (lane == 0) red[w] = c2;
    __syncthreads();
    if (t == 0) {
        float s = 0.0f;
#pragma unroll
        for (int r = 0; r < KSZ; r++) s += red[r];
        g_sq[c] = s;
        s_cinv = rsqrtf(s);
    }
    __syncthreads();
    float cinv = s_cinv;

    // per-row distance to normalized center
    float ds = 0.0f;
#pragma unroll
    for (int i = 0; i < 8; i++) {
        int d = lane + 32 * i;
        float diff = xn[w][d] - cen[d] * cinv;
        ds += diff * diff;
    }
#pragma unroll
    for (int o = 16; o; o >>= 1) ds += __shfl_xor_sync(0xffffffffu, ds, o);
    if (lane == 0) red[w] = sqrtf(ds);
    __syncthreads();
    if (t == 0) {
        float s = 0.0f;
#pragma unroll
        for (int r = 0; r < KSZ; r++) s += red[r];
        atomicAdd(&g_acc[0], s);
    }
}

// Upper-triangle tiled C*C^T (64x64 tiles, 4x4 per thread), fused hinge sum.
__global__ void pair_kernel() {
    int bi = blockIdx.y, bj = blockIdx.x;
    if (bj < bi) return;

    __shared__ float As[64][68];   // transposed: As[k][row]
    __shared__ float Bs[64][68];

    int t = threadIdx.x;
    int tx = t & 15, ty = t >> 4;

    float acc[4][4];
#pragma unroll
    for (int r = 0; r < 4; r++)
#pragma unroll
        for (int s = 0; s < 4; s++) acc[r][s] = 0.0f;

    for (int kc = 0; kc < DIM; kc += 64) {
#pragma unroll
        for (int l = 0; l < 4; l++) {
            int idx  = t + 256 * l;        // 0..1023 float4 slots
            int row  = idx >> 4;
            int col4 = (idx & 15) * 4;
            float4 a = *(const float4*)&g_centers[(bi * 64 + row) * DIM + kc + col4];
            As[col4 + 0][row] = a.x;
            As[col4 + 1][row] = a.y;
            As[col4 + 2][row] = a.z;
            As[col4 + 3][row] = a.w;
            float4 b = *(const float4*)&g_centers[(bj * 64 + row) * DIM + kc + col4];
            Bs[col4 + 0][row] = b.x;
            Bs[col4 + 1][row] = b.y;
            Bs[col4 + 2][row] = b.z;
            Bs[col4 + 3][row] = b.w;
        }
        __syncthreads();

#pragma unroll 16
        for (int k = 0; k < 64; k++) {
            float4 a4 = *(const float4*)&As[k][ty * 4];
            float4 b4 = *(const float4*)&Bs[k][tx * 4];
            float av[4] = {a4.x, a4.y, a4.z, a4.w};
            float bv[4] = {b4.x, b4.y, b4.z, b4.w};
#pragma unroll
            for (int r = 0; r < 4; r++)
#pragma unroll
                for (int s = 0; s < 4; s++) acc[r][s] = fmaf(av[r], bv[s], acc[r][s]);
        }
        __syncthreads();
    }

    int i0 = bi * 64 + ty * 4, j0 = bj * 64 + tx * 4;
    float sqi[4], sqj[4];
#pragma unroll
    for (int r = 0; r < 4; r++) sqi[r] = g_sq[i0 + r];
#pragma unroll
    for (int s = 0; s < 4; s++) sqj[s] = g_sq[j0 + s];

    float local = 0.0f;
#pragma unroll
    for (int r = 0; r < 4; r++) {
#pragma unroll
        for (int s = 0; s < 4; s++) {
            int i = i0 + r, j = j0 + s;
            if (j > i) {
                float d2 = sqi[r] + sqj[s] - 2.0f * acc[r][s];
                float d  = sqrtf(fmaxf(d2, 1e-12f));
                local += fmaxf(0.7f - d, 0.0f);
            }
        }
    }
#pragma unroll
    for (int o = 16; o; o >>= 1) local += __shfl_xor_sync(0xffffffffu, local, o);

    __shared__ float rs[8];
    if ((t & 31) == 0) rs[t >> 5] = local;
    __syncthreads();
    if (t == 0) {
        float s = 0.0f;
#pragma unroll
        for (int w = 0; w < 8; w++) s += rs[w];
        atomicAdd(&g_acc[1], s);
    }
}

__global__ void final_kernel(float* __restrict__ out) {
    float pc = g_acc[0] * (1.0f / (float)NSAMP);
    // dist_an_mean = (2*S) * K / ((N-K) * NCLASS)
    float an = g_acc[1] * (2.0f * (float)KSZ / ((float)(NSAMP - KSZ) * (float)NCLASS));
    out[0] = pc + an;
    out[1] = pc;
    out[2] = an;
}

extern "C" void kernel_launch(void* const* d_in, const int* in_sizes, int n_in,
                              void* d_out, int out_size) {
    const float* x = (const float*)d_in[0];
    float* out = (float*)d_out;
    zero_kernel<<<1, 32>>>();
    class_kernel<<<NCLASS, 256>>>(x);
    pair_kernel<<<dim3(16, 16), 256>>>();
    final_kernel<<<1, 1>>>(out);
}

// round 3
// speedup vs baseline: 1.7893x; 1.7893x over previous
#include <cuda_runtime.h>
#include <cuda_bf16.h>
#include <cstdint>

#define NCLASS 1024
#define DIM    256
#define KSZ    8
#define NSAMP  8192
#define NTILE  8          // 8x8 tiles of 128
#define TS     128        // tile size

// ---------------- scratch (no allocations allowed) ----------------
__device__ __align__(16) __nv_bfloat16 g_cbf[NCLASS * DIM];
__device__ float g_sq[NCLASS];
__device__ float g_pc[NCLASS];          // per-class dist_pc partial
__device__ float g_ph[NTILE * NTILE];   // per-tile hinge partial
__device__ unsigned g_cnt = 0;          // completion counter (self-resetting)

__device__ __forceinline__ uint32_t smem_u32(const void* p) {
    uint32_t a;
    asm("{ .reg .u64 t; cvta.to.shared.u64 t, %1; cvt.u32.u64 %0, t; }" : "=r"(a) : "l"(p));
    return a;
}
__device__ __forceinline__ void ldm_x4(uint32_t* r, uint32_t addr) {
    asm volatile("ldmatrix.sync.aligned.m8n8.x4.shared.b16 {%0,%1,%2,%3}, [%4];"
                 : "=r"(r[0]), "=r"(r[1]), "=r"(r[2]), "=r"(r[3]) : "r"(addr));
}
__device__ __forceinline__ void mma16816(float* d, const uint32_t* a, uint32_t b0, uint32_t b1) {
    asm volatile(
        "mma.sync.aligned.m16n8k16.row.col.f32.bf16.bf16.f32 "
        "{%0,%1,%2,%3}, {%4,%5,%6,%7}, {%8,%9}, {%0,%1,%2,%3};"
        : "+f"(d[0]), "+f"(d[1]), "+f"(d[2]), "+f"(d[3])
        : "r"(a[0]), "r"(a[1]), "r"(a[2]), "r"(a[3]), "r"(b0), "r"(b1));
}

// ---------------- kernel 1: per-class normalize / center / dist_pc ----------------
__global__ void class_kernel(const float* __restrict__ x) {
    int c = blockIdx.x;
    int t = threadIdx.x;
    int w = t >> 5, lane = t & 31;

    __shared__ float xn[KSZ][DIM];
    __shared__ float cen[DIM];
    __shared__ float red[KSZ];
    __shared__ float s_cinv;

    const float* row = x + (size_t)(c * KSZ + w) * DIM;
    float v[8];
    float ss = 0.0f;
#pragma unroll
    for (int i = 0; i < 8; i++) { v[i] = row[lane + 32 * i]; ss += v[i] * v[i]; }
#pragma unroll
    for (int o = 16; o; o >>= 1) ss += __shfl_xor_sync(0xffffffffu, ss, o);
    float inv = rsqrtf(ss);
#pragma unroll
    for (int i = 0; i < 8; i++) { v[i] *= inv; xn[w][lane + 32 * i] = v[i]; }
    __syncthreads();

    float cs = 0.0f;
#pragma unroll
    for (int r = 0; r < KSZ; r++) cs += xn[r][t];
    cs *= (1.0f / KSZ);
    cen[t] = cs;
    g_cbf[c * DIM + t] = __float2bfloat16(cs);

    float c2 = cs * cs;
#pragma unroll
    for (int o = 16; o; o >>= 1) c2 += __shfl_xor_sync(0xffffffffu, c2, o);
    if (lane == 0) red[w] = c2;
    __syncthreads();
    if (t == 0) {
        float s = 0.0f;
#pragma unroll
        for (int r = 0; r < KSZ; r++) s += red[r];
        g_sq[c] = s;
        s_cinv = rsqrtf(s);
    }
    __syncthreads();
    float cinv = s_cinv;

    float ds = 0.0f;
#pragma unroll
    for (int i = 0; i < 8; i++) {
        int d = lane + 32 * i;
        float diff = xn[w][d] - cen[d] * cinv;
        ds += diff * diff;
    }
#pragma unroll
    for (int o = 16; o; o >>= 1) ds += __shfl_xor_sync(0xffffffffu, ds, o);
    if (lane == 0) red[w] = sqrtf(ds);
    __syncthreads();
    if (t == 0) {
        float s = 0.0f;
#pragma unroll
        for (int r = 0; r < KSZ; r++) s += red[r];
        g_pc[c] = s;
    }
}

// ---------------- kernel 2: bf16 MMA pair tiles + fused finalize ----------------
// dyn smem: A tile [0:64K), B tile [64K:128K). 128 rows x 256 bf16 (512B rows),
// 16B segments XOR-swizzled: byte = row*512 + ((seg ^ (row&7)) << 4)
#define SMA_BYTES 65536
#define SM_TOTAL  (2 * SMA_BYTES)

__global__ void __launch_bounds__(256, 1) pair_kernel(float* __restrict__ out) {
    int bi = blockIdx.y, bj = blockIdx.x;
    int bid = bi * NTILE + bj;
    int t = threadIdx.x;
    int wid = t >> 5, lane = t & 31;

    extern __shared__ __align__(16) char smem[];
    uint32_t sA = smem_u32(smem);
    uint32_t sB = sA + SMA_BYTES;

    __shared__ float s_sqi[TS], s_sqj[TS];
    __shared__ float rs[8];
    __shared__ bool s_last;

    bool active = (bj >= bi);
    if (active) {
        // ---- stage tiles (conflict-free swizzled writes, coalesced reads) ----
        const uint4* gA = (const uint4*)(g_cbf + (size_t)bi * TS * DIM);
        const uint4* gB = (const uint4*)(g_cbf + (size_t)bj * TS * DIM);
#pragma unroll
        for (int it = 0; it < 16; it++) {
            int idx = t + 256 * it;          // 0..4095 16B segments
            int row = idx >> 5;
            int seg = idx & 31;
            uint32_t off = (uint32_t)(row * 512 + ((seg ^ (row & 7)) << 4));
            *(uint4*)(smem + off) = gA[idx];
            *(uint4*)(smem + SMA_BYTES + off) = gB[idx];
        }
        if (t < TS) s_sqi[t] = g_sq[bi * TS + t];
        else if (t < 2 * TS) s_sqj[t - TS] = g_sq[bj * TS + (t - TS)];
        __syncthreads();

        // ---- MMA mainloop: warp tile 64x32 ----
        int wm = wid >> 2, wn = wid & 3;
        int m0 = wm * 64, n0 = wn * 32;
        int lr = lane & 15, lh = lane >> 4;

        float acc[4][4][4];
#pragma unroll
        for (int a = 0; a < 4; a++)
#pragma unroll
            for (int b = 0; b < 4; b++)
#pragma unroll
                for (int c = 0; c < 4; c++) acc[a][b][c] = 0.0f;

#pragma unroll
        for (int kk = 0; kk < 16; kk++) {
            uint32_t af[4][4], bf[2][4];
#pragma unroll
            for (int ma = 0; ma < 4; ma++) {
                int row = m0 + ma * 16 + lr;
                int seg = kk * 2 + lh;
                ldm_x4(af[ma], sA + row * 512 + ((seg ^ (row & 7)) << 4));
            }
#pragma unroll
            for (int nb = 0; nb < 2; nb++) {
                int row = n0 + nb * 16 + lr;
                int seg = kk * 2 + lh;
                ldm_x4(bf[nb], sB + row * 512 + ((seg ^ (row & 7)) << 4));
            }
#pragma unroll
            for (int ma = 0; ma < 4; ma++)
#pragma unroll
                for (int nb = 0; nb < 2; nb++) {
                    mma16816(acc[ma][nb * 2 + 0], af[ma], bf[nb][0], bf[nb][2]);
                    mma16816(acc[ma][nb * 2 + 1], af[ma], bf[nb][1], bf[nb][3]);
                }
        }

        // ---- epilogue: hinge over fragments ----
        int g = lane >> 2, tg = lane & 3;
        bool diag = (bi == bj);
        float local = 0.0f;
#pragma unroll
        for (int ma = 0; ma < 4; ma++) {
#pragma unroll
            for (int nn = 0; nn < 4; nn++) {
                int r0 = m0 + ma * 16 + g;
                int c0 = n0 + nn * 8 + tg * 2;
#pragma unroll
                for (int e = 0; e < 4; e++) {
                    int r = r0 + (e >> 1) * 8;
                    int c = c0 + (e & 1);
                    float dot = acc[ma][nn][e];
                    float d2 = s_sqi[r] + s_sqj[c] - 2.0f * dot;
                    float d = sqrtf(fmaxf(d2, 1e-12f));
                    float h = fmaxf(0.7f - d, 0.0f);
                    if (!diag || c > r) local += h;
                }
            }
        }
#pragma unroll
        for (int o = 16; o; o >>= 1) local += __shfl_xor_sync(0xffffffffu, local, o);
        if (lane == 0) rs[wid] = local;
        __syncthreads();
        if (t == 0) {
            float s = 0.0f;
#pragma unroll
            for (int w2 = 0; w2 < 8; w2++) s += rs[w2];
            g_ph[bid] = s;
        }
    } else {
        if (t == 0) g_ph[bid] = 0.0f;
    }

    // ---- completion counter: last block finalizes ----
    __threadfence();
    __syncthreads();
    if (t == 0) s_last = (atomicAdd(&g_cnt, 1u) == (unsigned)(NTILE * NTILE - 1));
    __syncthreads();
    if (!s_last) return;

    float s1 = 0.0f, s2 = 0.0f;
#pragma unroll
    for (int i = t; i < NCLASS; i += 256) s1 += g_pc[i];
    if (t < NTILE * NTILE) s2 += g_ph[t];
#pragma unroll
    for (int o = 16; o; o >>= 1) {
        s1 += __shfl_xor_sync(0xffffffffu, s1, o);
        s2 += __shfl_xor_sync(0xffffffffu, s2, o);
    }
    __shared__ float r1[8], r2[8];
    if (lane == 0) { r1[wid] = s1; r2[wid] = s2; }
    __syncthreads();
    if (t == 0) {
        float a = 0.0f, b = 0.0f;
#pragma unroll
        for (int w2 = 0; w2 < 8; w2++) { a += r1[w2]; b += r2[w2]; }
        float pc = a * (1.0f / (float)NSAMP);
        float an = b * (2.0f * (float)KSZ / ((float)(NSAMP - KSZ) * (float)NCLASS));
        out[0] = pc + an;
        out[1] = pc;
        out[2] = an;
        g_cnt = 0;   // reset for next graph replay
    }
}

extern "C" void kernel_launch(void* const* d_in, const int* in_sizes, int n_in,
                              void* d_out, int out_size) {
    const float* x = (const float*)d_in[0];
    float* out = (float*)d_out;

    static bool attr_set = false;
    if (!attr_set) {
        cudaFuncSetAttribute(pair_kernel, cudaFuncAttributeMaxDynamicSharedMemorySize, SM_TOTAL);
        attr_set = true;
    }

    class_kernel<<<NCLASS, 256>>>(x);
    pair_kernel<<<dim3(NTILE, NTILE), 256, SM_TOTAL>>>(out);
}

// round 4
// speedup vs baseline: 2.7600x; 1.5425x over previous
#include <cuda_runtime.h>
#include <cuda_bf16.h>
#include <cstdint>

#define NCLASS 1024
#define DIM    256
#define KSZ    8
#define NSAMP  8192
#define TTILE  16         // 16x16 tiles of 64
#define TS     64         // tile size
#define NPAIR  136        // upper-triangle tile count (16*17/2)

// ---------------- scratch (no allocations allowed) ----------------
__device__ __align__(16) __nv_bfloat16 g_cbf[NCLASS * DIM];
__device__ float g_sq[NCLASS];
__device__ float g_pc[NCLASS];       // per-class dist_pc partial
__device__ float g_ph[NPAIR];        // per-tile hinge partial
__device__ unsigned g_cnt = 0;       // completion counter (self-resetting)

__device__ __forceinline__ uint32_t smem_u32(const void* p) {
    uint32_t a;
    asm("{ .reg .u64 t; cvta.to.shared.u64 t, %1; cvt.u32.u64 %0, t; }" : "=r"(a) : "l"(p));
    return a;
}
__device__ __forceinline__ void ldm_x4(uint32_t* r, uint32_t addr) {
    asm volatile("ldmatrix.sync.aligned.m8n8.x4.shared.b16 {%0,%1,%2,%3}, [%4];"
                 : "=r"(r[0]), "=r"(r[1]), "=r"(r[2]), "=r"(r[3]) : "r"(addr));
}
__device__ __forceinline__ void mma16816(float* d, const uint32_t* a, uint32_t b0, uint32_t b1) {
    asm volatile(
        "mma.sync.aligned.m16n8k16.row.col.f32.bf16.bf16.f32 "
        "{%0,%1,%2,%3}, {%4,%5,%6,%7}, {%8,%9}, {%0,%1,%2,%3};"
        : "+f"(d[0]), "+f"(d[1]), "+f"(d[2]), "+f"(d[3])
        : "r"(a[0]), "r"(a[1]), "r"(a[2]), "r"(a[3]), "r"(b0), "r"(b1));
}
__device__ __forceinline__ float warp_sum(float v) {
#pragma unroll
    for (int o = 16; o; o >>= 1) v += __shfl_xor_sync(0xffffffffu, v, o);
    return v;
}

// ---------------- kernel 1: warp-per-class normalize / center / dist_pc ----------------
// Lane owns 8 contiguous dims [8*lane, 8*lane+8). No smem, no __syncthreads.
__global__ void __launch_bounds__(256) class_kernel(const float* __restrict__ x) {
    int wid = threadIdx.x >> 5, lane = threadIdx.x & 31;
    int c = blockIdx.x * 8 + wid;

    const float4* base = (const float4*)(x + (size_t)c * KSZ * DIM) + lane * 2;

    float xn[KSZ][8];
    float cen[8] = {0, 0, 0, 0, 0, 0, 0, 0};

#pragma unroll
    for (int r = 0; r < KSZ; r++) {
        float4 a = base[r * (DIM / 4)];
        float4 b = base[r * (DIM / 4) + 1];
        float v[8] = {a.x, a.y, a.z, a.w, b.x, b.y, b.z, b.w};
        float ss = 0.0f;
#pragma unroll
        for (int i = 0; i < 8; i++) ss += v[i] * v[i];
        ss = warp_sum(ss);
        float inv = rsqrtf(ss);
#pragma unroll
        for (int i = 0; i < 8; i++) {
            float nv = v[i] * inv;
            xn[r][i] = nv;
            cen[i] += nv;
        }
    }
#pragma unroll
    for (int i = 0; i < 8; i++) cen[i] *= (1.0f / KSZ);

    // bf16 center store: 8 bf16 = 16B per lane, fully coalesced
    {
        uint32_t pk[4];
#pragma unroll
        for (int i = 0; i < 4; i++) {
            __nv_bfloat162 p = __float22bfloat162_rn(make_float2(cen[2 * i], cen[2 * i + 1]));
            pk[i] = *(uint32_t*)&p;
        }
        *(uint4*)(g_cbf + (size_t)c * DIM + lane * 8) = make_uint4(pk[0], pk[1], pk[2], pk[3]);
    }

    float c2 = 0.0f;
#pragma unroll
    for (int i = 0; i < 8; i++) c2 += cen[i] * cen[i];
    c2 = warp_sum(c2);
    if (lane == 0) g_sq[c] = c2;
    float cinv = rsqrtf(c2);

    float pcsum = 0.0f;
#pragma unroll
    for (int r = 0; r < KSZ; r++) {
        float ds = 0.0f;
#pragma unroll
        for (int i = 0; i < 8; i++) {
            float diff = xn[r][i] - cen[i] * cinv;
            ds += diff * diff;
        }
        ds = warp_sum(ds);
        pcsum += sqrtf(ds);
    }
    if (lane == 0) g_pc[c] = pcsum;
}

// ---------------- kernel 2: bf16 MMA 64x64 pair tiles + fused finalize ----------------
// smem per tile: 64 rows x 256 bf16 (512B rows), 16B segs XOR-swizzled:
// byte = row*512 + ((seg ^ (row&7)) << 4)
#define SMA_BYTES 32768
#define SM_TOTAL  (2 * SMA_BYTES)

__global__ void __launch_bounds__(256, 1) pair_kernel(float* __restrict__ out) {
    int t = threadIdx.x;
    int wid = t >> 5, lane = t & 31;

    // triangular bid -> (bi, bj), bj >= bi
    int bid = blockIdx.x;
    int bi = 0, off = 0;
    while (bid >= off + (TTILE - bi)) { off += TTILE - bi; bi++; }
    int bj = bi + (bid - off);

    extern __shared__ __align__(16) char smem[];
    uint32_t sA = smem_u32(smem);
    uint32_t sB = sA + SMA_BYTES;

    __shared__ float s_sqi[TS], s_sqj[TS];
    __shared__ float rs[8];
    __shared__ bool s_last;

    // ---- stage tiles: 2 x 64 rows x 32 segs = 4096 segs, 16 per thread ----
    {
        const uint4* gA = (const uint4*)(g_cbf + (size_t)bi * TS * DIM);
        const uint4* gB = (const uint4*)(g_cbf + (size_t)bj * TS * DIM);
#pragma unroll
        for (int it = 0; it < 8; it++) {
            int idx = t + 256 * it;          // 0..2047 segs per tile
            int row = idx >> 5;
            int seg = idx & 31;
            uint32_t o = (uint32_t)(row * 512 + ((seg ^ (row & 7)) << 4));
            *(uint4*)(smem + o) = gA[idx];
            *(uint4*)(smem + SMA_BYTES + o) = gB[idx];
        }
    }
    if (t < TS) s_sqi[t] = g_sq[bi * TS + t];
    else if (t < 2 * TS) s_sqj[t - TS] = g_sq[bj * TS + (t - TS)];
    __syncthreads();

    // ---- MMA mainloop: warp tile 32x16 (2 warps M x 4 warps N) ----
    int wm = wid >> 2, wn = wid & 3;
    int m0 = wm * 32, n0 = wn * 16;
    int lr = lane & 15, lh = lane >> 4;

    float acc[2][2][4];
#pragma unroll
    for (int a = 0; a < 2; a++)
#pragma unroll
        for (int b = 0; b < 2; b++)
#pragma unroll
            for (int e = 0; e < 4; e++) acc[a][b][e] = 0.0f;

#pragma unroll
    for (int kk = 0; kk < 16; kk++) {
        uint32_t af[2][4], bf[4];
        int seg = kk * 2 + lh;
#pragma unroll
        for (int ma = 0; ma < 2; ma++) {
            int row = m0 + ma * 16 + lr;
            ldm_x4(af[ma], sA + row * 512 + ((seg ^ (row & 7)) << 4));
        }
        {
            int row = n0 + lr;
            ldm_x4(bf, sB + row * 512 + ((seg ^ (row & 7)) << 4));
        }
#pragma unroll
        for (int ma = 0; ma < 2; ma++) {
            mma16816(acc[ma][0], af[ma], bf[0], bf[2]);
            mma16816(acc[ma][1], af[ma], bf[1], bf[3]);
        }
    }

    // ---- epilogue: hinge over fragments ----
    int g = lane >> 2, tg = lane & 3;
    bool diag = (bi == bj);
    float local = 0.0f;
#pragma unroll
    for (int ma = 0; ma < 2; ma++) {
#pragma unroll
        for (int nn = 0; nn < 2; nn++) {
            int r0 = m0 + ma * 16 + g;
            int c0 = n0 + nn * 8 + tg * 2;
#pragma unroll
            for (int e = 0; e < 4; e++) {
                int r = r0 + (e >> 1) * 8;
                int c = c0 + (e & 1);
                float dot = acc[ma][nn][e];
                float d2 = s_sqi[r] + s_sqj[c] - 2.0f * dot;
                float d = sqrtf(fmaxf(d2, 1e-12f));
                float h = fmaxf(0.7f - d, 0.0f);
                if (!diag || c > r) local += h;
            }
        }
    }
    local = warp_sum(local);
    if (lane == 0) rs[wid] = local;
    __syncthreads();
    if (t == 0) {
        float s = 0.0f;
#pragma unroll
        for (int w2 = 0; w2 < 8; w2++) s += rs[w2];
        g_ph[bid] = s;
    }

    // ---- completion counter: last block finalizes ----
    __threadfence();
    __syncthreads();
    if (t == 0) s_last = (atomicAdd(&g_cnt, 1u) == (unsigned)(NPAIR - 1));
    __syncthreads();
    if (!s_last) return;

    float s1 = 0.0f, s2 = 0.0f;
#pragma unroll
    for (int i = t; i < NCLASS; i += 256) s1 += g_pc[i];
    if (t < NPAIR) s2 += g_ph[t];
    s1 = warp_sum(s1);
    s2 = warp_sum(s2);
    __shared__ float r1[8], r2[8];
    if (lane == 0) { r1[wid] = s1; r2[wid] = s2; }
    __syncthreads();
    if (t == 0) {
        float a = 0.0f, b = 0.0f;
#pragma unroll
        for (int w2 = 0; w2 < 8; w2++) { a += r1[w2]; b += r2[w2]; }
        float pc = a * (1.0f / (float)NSAMP);
        float an = b * (2.0f * (float)KSZ / ((float)(NSAMP - KSZ) * (float)NCLASS));
        out[0] = pc + an;
        out[1] = pc;
        out[2] = an;
        g_cnt = 0;   // reset for next graph replay
    }
}

extern "C" void kernel_launch(void* const* d_in, const int* in_sizes, int n_in,
                              void* d_out, int out_size) {
    const float* x = (const float*)d_in[0];
    float* out = (float*)d_out;

    static bool attr_set = false;
    if (!attr_set) {
        cudaFuncSetAttribute(pair_kernel, cudaFuncAttributeMaxDynamicSharedMemorySize, SM_TOTAL);
        attr_set = true;
    }

    class_kernel<<<NCLASS / 8, 256>>>(x);
    pair_kernel<<<NPAIR, 256, SM_TOTAL>>>(out);
}